// round 6
// baseline (speedup 1.0000x reference)
#include <cuda_runtime.h>
#include <math.h>
#include <stdint.h>

// Problem: s=4096, b=8, D=1280, H=16, DH=80, W=64, nw=64
// QKV GEMM : M=32768, N=3840, K=1280  (NT, both K-major)
// ATTN     : 32768 independent 16x16x80 attention problems
// PROJ GEMM: M=8192,  N=1280, K=5120  (NT)

#define CTA_M 128
#define CTA_N 256
#define STAGES 4
#define STAGE_BYTES 24576          // A 8KB + B 16KB  (BK=16, f32)
#define A_OFF 0
#define B_OFF 8192

// Scratch (device globals; no runtime allocation allowed)
__device__ float g_qkv[125829120ull];   // 32768 * 3840
__device__ float g_attn[41943040ull];   // 8192 * 5120

__device__ __forceinline__ uint32_t f2tf32(float x) {
    uint32_t r;
    asm("cvt.rna.tf32.f32 %0, %1;" : "=r"(r) : "f"(x));
    return r;
}
__device__ __forceinline__ void cp16(uint32_t smem_dst, const void* gptr) {
    asm volatile("cp.async.cg.shared.global [%0], [%1], 16;"
                 :: "r"(smem_dst), "l"(gptr) : "memory");
}

// ---------------------------------------------------------------------------
// C[M,N] = A[M,K] * B[N,K]^T + bias[N], tf32 mma.sync, fp32 accumulate.
// CTA 128x256, 8 warps (2x4), warp tile 64x64, BK=16.
// 4-stage cp.async pipeline; smem chunk-major [kgroup][row][16B] so every
// fragment LDS.32 is a warp access to 128 contiguous bytes (conflict-free).
// f32 -> tf32 cvt happens on the fragment path (fma/alu pipes are idle).
// ---------------------------------------------------------------------------
__global__ __launch_bounds__(256, 1) void tgemm_nt_bias(
    const float* __restrict__ A, const float* __restrict__ B,
    const float* __restrict__ bias, float* __restrict__ C,
    int M, int N, int K)
{
    extern __shared__ __align__(16) char smc[];   // STAGES * STAGE_BYTES
    const uint32_t sbase = (uint32_t)__cvta_generic_to_shared(smc);

    const int tid  = threadIdx.x;
    const int wid  = tid >> 5;
    const int lane = tid & 31;
    const int grp  = lane >> 2;   // 0..7
    const int qid  = lane & 3;    // 0..3

    const int wm = (wid & 1) * 64;   // warp rows
    const int wn = (wid >> 1) * 64;  // warp cols

    const float* Ab = A + (size_t)blockIdx.y * CTA_M * K;
    const float* Bb = B + (size_t)blockIdx.x * CTA_N * K;

    // staging decode: A chunks c = tid, tid+256 ; B chunks c = tid + i*256
    const int ar0 = tid >> 2, akg = (tid & 3) * 4;     // A row / k-offset

    float acc[4][8][4];
#pragma unroll
    for (int i = 0; i < 4; i++)
#pragma unroll
        for (int j = 0; j < 8; j++)
#pragma unroll
            for (int c = 0; c < 4; c++) acc[i][j][c] = 0.f;

    const int nk = K >> 4;

#define ISSUE_STAGE(kt_)                                                       \
    do {                                                                       \
        const uint32_t sb = sbase + ((kt_) & (STAGES - 1)) * STAGE_BYTES;      \
        const int k0 = (kt_) << 4;                                             \
        cp16(sb + A_OFF + ((akg >> 2) * 128 + ar0) * 16,                       \
             Ab + (size_t)ar0 * K + k0 + akg);                                 \
        cp16(sb + A_OFF + ((akg >> 2) * 128 + ar0 + 64) * 16,                  \
             Ab + (size_t)(ar0 + 64) * K + k0 + akg);                          \
        _Pragma("unroll") for (int i = 0; i < 4; i++) {                        \
            const int row = ar0 + i * 64;                                      \
            cp16(sb + B_OFF + ((akg >> 2) * 256 + row) * 16,                   \
                 Bb + (size_t)row * K + k0 + akg);                             \
        }                                                                      \
        asm volatile("cp.async.commit_group;" ::: "memory");                   \
    } while (0)

    // prologue: stages 0..2 in flight
    ISSUE_STAGE(0);
    ISSUE_STAGE(1);
    ISSUE_STAGE(2);

    for (int kt = 0; kt < nk; kt++) {
        if (kt + 3 < nk)      asm volatile("cp.async.wait_group 3;" ::: "memory");
        else if (kt + 1 < nk) asm volatile("cp.async.wait_group 1;" ::: "memory");
        else                  asm volatile("cp.async.wait_group 0;" ::: "memory");
        __syncthreads();

        if (kt + 3 < nk) ISSUE_STAGE(kt + 3);

        const char* buf = smc + (kt & (STAGES - 1)) * STAGE_BYTES;
        const float* abuf = (const float*)(buf + A_OFF);
        const float* bbuf = (const float*)(buf + B_OFF);

#pragma unroll
        for (int kc = 0; kc < 2; kc++) {
            const int kg0 = kc * 2;
            uint32_t af[4][4];
#pragma unroll
            for (int mf = 0; mf < 4; mf++) {
                const int rb = wm + mf * 16 + grp;
                af[mf][0] = f2tf32(abuf[(kg0 * 128 + rb) * 4 + qid]);
                af[mf][1] = f2tf32(abuf[(kg0 * 128 + rb + 8) * 4 + qid]);
                af[mf][2] = f2tf32(abuf[((kg0 + 1) * 128 + rb) * 4 + qid]);
                af[mf][3] = f2tf32(abuf[((kg0 + 1) * 128 + rb + 8) * 4 + qid]);
            }
#pragma unroll
            for (int np = 0; np < 8; np++) {
                const int nr = wn + np * 8 + grp;
                uint32_t b0 = f2tf32(bbuf[(kg0 * 256 + nr) * 4 + qid]);
                uint32_t b1 = f2tf32(bbuf[((kg0 + 1) * 256 + nr) * 4 + qid]);
#pragma unroll
                for (int mf = 0; mf < 4; mf++) {
                    asm volatile(
                        "mma.sync.aligned.m16n8k8.row.col.f32.tf32.tf32.f32 "
                        "{%0,%1,%2,%3}, {%4,%5,%6,%7}, {%8,%9}, {%0,%1,%2,%3};"
                        : "+f"(acc[mf][np][0]), "+f"(acc[mf][np][1]),
                          "+f"(acc[mf][np][2]), "+f"(acc[mf][np][3])
                        : "r"(af[mf][0]), "r"(af[mf][1]),
                          "r"(af[mf][2]), "r"(af[mf][3]),
                          "r"(b0), "r"(b1));
                }
            }
        }
        __syncthreads();
    }

    // epilogue: bias + float2 stores
#pragma unroll
    for (int mf = 0; mf < 4; mf++) {
        const int row0 = blockIdx.y * CTA_M + wm + mf * 16 + grp;
#pragma unroll
        for (int np = 0; np < 8; np++) {
            const int col = blockIdx.x * CTA_N + wn + np * 8 + qid * 2;
            const float bv0 = bias[col], bv1 = bias[col + 1];
            float2 r0 = make_float2(acc[mf][np][0] + bv0, acc[mf][np][1] + bv1);
            float2 r1 = make_float2(acc[mf][np][2] + bv0, acc[mf][np][3] + bv1);
            *(float2*)(C + (size_t)row0 * N + col) = r0;
            *(float2*)(C + (size_t)(row0 + 8) * N + col) = r1;
        }
    }
#undef ISSUE_STAGE
}

// ---------------------------------------------------------------------------
// Windowed attention: one block per qkv row r = (n*64+w)*8 + b.
// S[h,g] = q_h . k_g / sqrt(80); softmax over g; O = P V.
// Scatter-writes the rearranged (nw*H, b, W*DH) layout.
// ---------------------------------------------------------------------------
__global__ __launch_bounds__(256) void attn_kernel(const float* __restrict__ qkv,
                                                   float* __restrict__ O2)
{
    __shared__ float qs[16 * 84];
    __shared__ float ks[16 * 84];
    __shared__ float vs[16 * 84];
    __shared__ float sc[16][17];

    const int r    = blockIdx.x;
    const int b    = r & 7;
    const int sidx = r >> 3;
    const int w    = sidx & 63;
    const int n    = sidx >> 6;
    const int tid  = threadIdx.x;

    const float* row = qkv + (size_t)r * 3840;
    for (int i = tid; i < 1280; i += 256) {
        int h = i / 80, d = i - h * 80;
        qs[h * 84 + d] = row[i];
        ks[h * 84 + d] = row[1280 + i];
        vs[h * 84 + d] = row[2560 + i];
    }
    __syncthreads();

    {
        const int h = tid >> 4, g = tid & 15;
        const float* qh = qs + h * 84;
        const float* kg = ks + g * 84;
        float s = 0.f;
#pragma unroll
        for (int d = 0; d < 80; d++) s = fmaf(qh[d], kg[d], s);
        sc[h][g] = s * 0.11180339887498948f;
    }
    __syncthreads();

    if (tid < 16) {
        float m = sc[tid][0];
#pragma unroll
        for (int g = 1; g < 16; g++) m = fmaxf(m, sc[tid][g]);
        float sum = 0.f;
#pragma unroll
        for (int g = 0; g < 16; g++) {
            float e = expf(sc[tid][g] - m);
            sc[tid][g] = e;
            sum += e;
        }
        float inv = 1.f / sum;
#pragma unroll
        for (int g = 0; g < 16; g++) sc[tid][g] *= inv;
    }
    __syncthreads();

    float* obase = O2 + ((size_t)(n * 16) * 8 + b) * 5120 + (size_t)w * 80;
    for (int i = tid; i < 1280; i += 256) {
        int h = i / 80, d = i - h * 80;
        float o = 0.f;
#pragma unroll
        for (int g = 0; g < 16; g++) o = fmaf(sc[h][g], vs[g * 84 + d], o);
        obase[(size_t)h * 8 * 5120 + d] = o;
    }
}

// ---------------------------------------------------------------------------
// Launcher
// Inputs: 0=x (4096,8,1280) f32, 1=cu_seqlens i64 (ignored), 2=qkv_w (3840,1280),
//         3=qkv_b (3840), 4=proj_w (1280,5120), 5=proj_b (1280)
// Output: (1024, 8, 1280) f32
// ---------------------------------------------------------------------------
extern "C" void kernel_launch(void* const* d_in, const int* in_sizes, int n_in,
                              void* d_out, int out_size)
{
    const float* x      = (const float*)d_in[0];
    const float* qkv_w  = (const float*)d_in[2];
    const float* qkv_b  = (const float*)d_in[3];
    const float* proj_w = (const float*)d_in[4];
    const float* proj_b = (const float*)d_in[5];
    float* out = (float*)d_out;

    float *qkv_buf, *attn_buf;
    cudaGetSymbolAddress((void**)&qkv_buf, g_qkv);
    cudaGetSymbolAddress((void**)&attn_buf, g_attn);

    const int smem_bytes = STAGES * STAGE_BYTES;   // 98304
    cudaFuncSetAttribute(tgemm_nt_bias,
                         cudaFuncAttributeMaxDynamicSharedMemorySize, smem_bytes);

    // 1) QKV projection: (32768 x 1280) @ (3840 x 1280)^T + bias
    tgemm_nt_bias<<<dim3(3840 / CTA_N, 32768 / CTA_M), 256, smem_bytes>>>(
        x, qkv_w, qkv_b, qkv_buf, 32768, 3840, 1280);

    // 2) Windowed attention over head axis, scatter to rearranged layout
    attn_kernel<<<32768, 256>>>(qkv_buf, attn_buf);

    // 3) Output projection: (8192 x 5120) @ (1280 x 5120)^T + bias -> d_out
    tgemm_nt_bias<<<dim3(1280 / CTA_N, 8192 / CTA_M), 256, smem_bytes>>>(
        attn_buf, proj_w, proj_b, out, 8192, 1280, 5120);
}

// round 9
// speedup vs baseline: 3.7661x; 3.7661x over previous
#include <cuda_runtime.h>
#include <cuda_fp16.h>
#include <math.h>
#include <stdint.h>

// Problem: s=4096, b=8, D=1280, H=16, DH=80, W=64, nw=64
// QKV GEMM : M=32768, N=3840, K=1280  (NT, both K-major)
// ATTN     : 32768 independent 16x16x80 attention problems
// PROJ GEMM: M=8192,  N=1280, K=5120  (NT)

#define CTA_M 128
#define CTA_N 128
#define BK 64
#define STAGES 3
#define A_BYTES 16384              // 128 rows * 128B (64 halves)
#define STAGE_BYTES 32768          // A 16KB + B 16KB

// Scratch (device globals; no runtime allocation allowed)
__device__ __half g_xh[41943040ull];     // x as fp16
__device__ __half g_qkvwh[4915200ull];   // qkv_w as fp16
__device__ __half g_projwh[6553600ull];  // proj_w as fp16
__device__ float  g_qkv[125829120ull];   // qkv output (f32, attn input)
__device__ __half g_attnh[41943040ull];  // attn output, rearranged, fp16

__device__ __forceinline__ void cp16(uint32_t smem_dst, const void* gptr) {
    asm volatile("cp.async.cg.shared.global [%0], [%1], 16;"
                 :: "r"(smem_dst), "l"(gptr) : "memory");
}
#define LDSM4(d, addr)                                                         \
    asm volatile("ldmatrix.sync.aligned.m8n8.x4.shared.b16 {%0,%1,%2,%3}, [%4];" \
                 : "=r"((d)[0]), "=r"((d)[1]), "=r"((d)[2]), "=r"((d)[3])      \
                 : "r"(addr))

// ---------------------------------------------------------------------------
// f32 -> fp16 elementwise convert (8 elems/thread)
// ---------------------------------------------------------------------------
__global__ void f2h_kernel(const float* __restrict__ in,
                           __half* __restrict__ out, int n) {
    int i = (blockIdx.x * blockDim.x + threadIdx.x) * 8;
    if (i < n) {
        float4 v0 = *(const float4*)(in + i);
        float4 v1 = *(const float4*)(in + i + 4);
        __half2 h[4];
        h[0] = __floats2half2_rn(v0.x, v0.y);
        h[1] = __floats2half2_rn(v0.z, v0.w);
        h[2] = __floats2half2_rn(v1.x, v1.y);
        h[3] = __floats2half2_rn(v1.z, v1.w);
        *(uint4*)(out + i) = *(uint4*)h;
    }
}

// ---------------------------------------------------------------------------
// C[M,N] = A[M,K] * B[N,K]^T + bias[N], fp16 mma m16n8k16, fp32 accumulate.
// CTA 128x128, 8 warps (2x4), warp tile 64x32, BK=64, 3-stage cp.async.
// XOR-swizzled fp16 tiles; fragments via ldmatrix.x4 (conflict-free).
// 2 CTAs/SM (regs capped by launch_bounds, 2x96KB smem).
// ---------------------------------------------------------------------------
__global__ __launch_bounds__(256, 2) void hgemm_nt_bias(
    const __half* __restrict__ A, const __half* __restrict__ B,
    const float* __restrict__ bias, float* __restrict__ C,
    int M, int N, int K)
{
    extern __shared__ __align__(16) char smc[];   // STAGES * STAGE_BYTES
    const uint32_t sbase = (uint32_t)__cvta_generic_to_shared(smc);

    const int tid  = threadIdx.x;
    const int wid  = tid >> 5;
    const int lane = tid & 31;
    const int grp  = lane >> 2;      // 0..7
    const int qid  = lane & 3;       // 0..3

    const int wm = (wid & 1) * 64;   // warp rows
    const int wn = (wid >> 1) * 32;  // warp cols

    const __half* Ab = A + (size_t)blockIdx.y * CTA_M * K;
    const __half* Bb = B + (size_t)blockIdx.x * CTA_N * K;

    // staging decode: thread -> (row sr + 32p, 16B-unit su)
    const int su = tid & 7;
    const int sr = tid >> 3;         // 0..31

    // ldmatrix per-thread row/unit decode
    const int a_r = (lane & 7) + ((lane >> 3) & 1) * 8;  // A: m0,m1=rows, m2,m3=+unit
    const int a_u = lane >> 4;
    const int b_r = (lane & 7) + ((lane >> 4) & 1) * 8;  // B: m0,m1=units, m2,m3=+rows
    const int b_u = (lane >> 3) & 1;

    float acc[4][4][4];
#pragma unroll
    for (int i = 0; i < 4; i++)
#pragma unroll
        for (int j = 0; j < 4; j++)
#pragma unroll
            for (int c = 0; c < 4; c++) acc[i][j][c] = 0.f;

    const int nk = K / BK;

#define ISSUE_STAGE(kt_)                                                       \
    do {                                                                       \
        const uint32_t sb = sbase + ((kt_) % STAGES) * STAGE_BYTES;            \
        const int k0 = (kt_) * BK;                                             \
        _Pragma("unroll") for (int p = 0; p < 4; p++) {                        \
            const int r = sr + p * 32;                                         \
            const uint32_t sw = (uint32_t)(r * 128 + ((su ^ (r & 7)) << 4));   \
            cp16(sb + sw, Ab + (size_t)r * K + k0 + su * 8);                   \
            cp16(sb + A_BYTES + sw, Bb + (size_t)r * K + k0 + su * 8);         \
        }                                                                      \
        asm volatile("cp.async.commit_group;" ::: "memory");                   \
    } while (0)

    ISSUE_STAGE(0);
    ISSUE_STAGE(1);

    for (int kt = 0; kt < nk; kt++) {
        if (kt + 2 < nk) asm volatile("cp.async.wait_group 1;" ::: "memory");
        else             asm volatile("cp.async.wait_group 0;" ::: "memory");
        __syncthreads();
        if (kt + 2 < nk) ISSUE_STAGE(kt + 2);

        const uint32_t abase = sbase + (kt % STAGES) * STAGE_BYTES;
        const uint32_t bbase = abase + A_BYTES;

#pragma unroll
        for (int kk = 0; kk < 4; kk++) {
            uint32_t a[4][4], b[2][4];
#pragma unroll
            for (int mf = 0; mf < 4; mf++) {
                const int r = wm + mf * 16 + a_r;
                const int u = kk * 2 + a_u;
                LDSM4(a[mf], abase + r * 128 + ((u ^ (r & 7)) << 4));
            }
#pragma unroll
            for (int nfp = 0; nfp < 2; nfp++) {
                const int r = wn + nfp * 16 + b_r;
                const int u = kk * 2 + b_u;
                LDSM4(b[nfp], bbase + r * 128 + ((u ^ (r & 7)) << 4));
            }
#pragma unroll
            for (int mf = 0; mf < 4; mf++)
#pragma unroll
                for (int nf = 0; nf < 4; nf++) {
                    asm volatile(
                        "mma.sync.aligned.m16n8k16.row.col.f32.f16.f16.f32 "
                        "{%0,%1,%2,%3}, {%4,%5,%6,%7}, {%8,%9}, {%0,%1,%2,%3};"
                        : "+f"(acc[mf][nf][0]), "+f"(acc[mf][nf][1]),
                          "+f"(acc[mf][nf][2]), "+f"(acc[mf][nf][3])
                        : "r"(a[mf][0]), "r"(a[mf][1]),
                          "r"(a[mf][2]), "r"(a[mf][3]),
                          "r"(b[nf >> 1][(nf & 1) * 2]),
                          "r"(b[nf >> 1][(nf & 1) * 2 + 1]));
                }
        }
    }

    // epilogue: bias + float2 stores
#pragma unroll
    for (int mf = 0; mf < 4; mf++) {
        const int row0 = blockIdx.y * CTA_M + wm + mf * 16 + grp;
#pragma unroll
        for (int nf = 0; nf < 4; nf++) {
            const int col = blockIdx.x * CTA_N + wn + nf * 8 + qid * 2;
            const float bv0 = bias[col], bv1 = bias[col + 1];
            float2 r0 = make_float2(acc[mf][nf][0] + bv0, acc[mf][nf][1] + bv1);
            float2 r1 = make_float2(acc[mf][nf][2] + bv0, acc[mf][nf][3] + bv1);
            *(float2*)(C + (size_t)row0 * N + col) = r0;
            *(float2*)(C + (size_t)(row0 + 8) * N + col) = r1;
        }
    }
#undef ISSUE_STAGE
}

// ---------------------------------------------------------------------------
// Windowed attention: one block per qkv row r = (n*64+w)*8 + b.
// S[h,g] = q_h . k_g / sqrt(80); softmax over g; O = P V.
// Scatter-writes fp16 into the rearranged (nw*H, b, W*DH) layout.
// ---------------------------------------------------------------------------
__global__ __launch_bounds__(256) void attn_kernel(const float* __restrict__ qkv,
                                                   __half* __restrict__ O2)
{
    __shared__ float qs[16 * 84];
    __shared__ float ks[16 * 84];
    __shared__ float vs[16 * 84];
    __shared__ float sc[16][17];

    const int r    = blockIdx.x;
    const int b    = r & 7;
    const int sidx = r >> 3;
    const int w    = sidx & 63;
    const int n    = sidx >> 6;
    const int tid  = threadIdx.x;

    const float* row = qkv + (size_t)r * 3840;
    for (int i = tid; i < 1280; i += 256) {
        int h = i / 80, d = i - h * 80;
        qs[h * 84 + d] = row[i];
        ks[h * 84 + d] = row[1280 + i];
        vs[h * 84 + d] = row[2560 + i];
    }
    __syncthreads();

    {
        const int h = tid >> 4, g = tid & 15;
        const float* qh = qs + h * 84;
        const float* kg = ks + g * 84;
        float s = 0.f;
#pragma unroll
        for (int d = 0; d < 80; d++) s = fmaf(qh[d], kg[d], s);
        sc[h][g] = s * 0.11180339887498948f;
    }
    __syncthreads();

    if (tid < 16) {
        float m = sc[tid][0];
#pragma unroll
        for (int g = 1; g < 16; g++) m = fmaxf(m, sc[tid][g]);
        float sum = 0.f;
#pragma unroll
        for (int g = 0; g < 16; g++) {
            float e = expf(sc[tid][g] - m);
            sc[tid][g] = e;
            sum += e;
        }
        float inv = 1.f / sum;
#pragma unroll
        for (int g = 0; g < 16; g++) sc[tid][g] *= inv;
    }
    __syncthreads();

    __half* obase = O2 + ((size_t)(n * 16) * 8 + b) * 5120 + (size_t)w * 80;
    for (int i = tid; i < 1280; i += 256) {
        int h = i / 80, d = i - h * 80;
        float o = 0.f;
#pragma unroll
        for (int g = 0; g < 16; g++) o = fmaf(sc[h][g], vs[g * 84 + d], o);
        obase[(size_t)h * 8 * 5120 + d] = __float2half(o);
    }
}

// ---------------------------------------------------------------------------
// Launcher
// Inputs: 0=x (4096,8,1280) f32, 1=cu_seqlens i64 (ignored), 2=qkv_w (3840,1280),
//         3=qkv_b (3840), 4=proj_w (1280,5120), 5=proj_b (1280)
// Output: (1024, 8, 1280) f32
// ---------------------------------------------------------------------------
extern "C" void kernel_launch(void* const* d_in, const int* in_sizes, int n_in,
                              void* d_out, int out_size)
{
    const float* x      = (const float*)d_in[0];
    const float* qkv_w  = (const float*)d_in[2];
    const float* qkv_b  = (const float*)d_in[3];
    const float* proj_w = (const float*)d_in[4];
    const float* proj_b = (const float*)d_in[5];
    float* out = (float*)d_out;

    __half *xh, *qkvwh, *projwh, *attnh;
    float* qkv_buf;
    cudaGetSymbolAddress((void**)&xh, g_xh);
    cudaGetSymbolAddress((void**)&qkvwh, g_qkvwh);
    cudaGetSymbolAddress((void**)&projwh, g_projwh);
    cudaGetSymbolAddress((void**)&qkv_buf, g_qkv);
    cudaGetSymbolAddress((void**)&attnh, g_attnh);

    const int smem_bytes = STAGES * STAGE_BYTES;   // 98304
    cudaFuncSetAttribute(hgemm_nt_bias,
                         cudaFuncAttributeMaxDynamicSharedMemorySize, smem_bytes);

    // 0) convert inputs to fp16
    f2h_kernel<<<20480, 256>>>(x, xh, 41943040);
    f2h_kernel<<<2400, 256>>>(qkv_w, qkvwh, 4915200);
    f2h_kernel<<<3200, 256>>>(proj_w, projwh, 6553600);

    // 1) QKV projection: (32768 x 1280) @ (3840 x 1280)^T + bias -> f32
    hgemm_nt_bias<<<dim3(3840 / CTA_N, 32768 / CTA_M), 256, smem_bytes>>>(
        xh, qkvwh, qkv_b, qkv_buf, 32768, 3840, 1280);

    // 2) Windowed attention over head axis, scatter fp16 rearranged layout
    attn_kernel<<<32768, 256>>>(qkv_buf, attnh);

    // 3) Output projection: (8192 x 5120) @ (1280 x 5120)^T + bias -> d_out
    hgemm_nt_bias<<<dim3(1280 / CTA_N, 8192 / CTA_M), 256, smem_bytes>>>(
        attnh, projwh, proj_b, out, 8192, 1280, 5120);
}

// round 10
// speedup vs baseline: 3.7978x; 1.0084x over previous
#include <cuda_runtime.h>
#include <cuda_fp16.h>
#include <math.h>
#include <stdint.h>

// Problem: s=4096, b=8, D=1280, H=16, DH=80, W=64, nw=64
// QKV GEMM : M=32768, N=3840, K=1280  (NT, both K-major) -> fp16 out
// ATTN     : 32768 independent 16x16x80 attention problems (fp16 in/out)
// PROJ GEMM: M=8192,  N=1280, K=5120  (NT) -> f32 out
#define CTA_M 128
#define CTA_N 128
#define BK 64
#define STAGES 3
#define A_BYTES 16384              // 128 rows * 128B (64 halves)
#define STAGE_BYTES 32768          // A 16KB + B 16KB

// Scratch (device globals; no runtime allocation allowed)
__device__ __half g_xh[41943040ull];     // x as fp16
__device__ __half g_qkvwh[4915200ull];   // qkv_w as fp16
__device__ __half g_projwh[6553600ull];  // proj_w as fp16
__device__ __half g_qkvh[125829120ull];  // qkv output (fp16, attn input)
__device__ __half g_attnh[41943040ull];  // attn output, rearranged, fp16

__device__ __forceinline__ void cp16(uint32_t smem_dst, const void* gptr) {
    asm volatile("cp.async.cg.shared.global [%0], [%1], 16;"
                 :: "r"(smem_dst), "l"(gptr) : "memory");
}
#define LDSM4(d, addr)                                                         \
    asm volatile("ldmatrix.sync.aligned.m8n8.x4.shared.b16 {%0,%1,%2,%3}, [%4];" \
                 : "=r"((d)[0]), "=r"((d)[1]), "=r"((d)[2]), "=r"((d)[3])      \
                 : "r"(addr))

// ---------------------------------------------------------------------------
// f32 -> fp16 elementwise convert (8 elems/thread)
// ---------------------------------------------------------------------------
__global__ void f2h_kernel(const float* __restrict__ in,
                           __half* __restrict__ out, int n) {
    int i = (blockIdx.x * blockDim.x + threadIdx.x) * 8;
    if (i < n) {
        float4 v0 = *(const float4*)(in + i);
        float4 v1 = *(const float4*)(in + i + 4);
        __half2 h[4];
        h[0] = __floats2half2_rn(v0.x, v0.y);
        h[1] = __floats2half2_rn(v0.z, v0.w);
        h[2] = __floats2half2_rn(v1.x, v1.y);
        h[3] = __floats2half2_rn(v1.z, v1.w);
        *(uint4*)(out + i) = *(uint4*)h;
    }
}

// ---------------------------------------------------------------------------
// C[M,N] = A[M,K] * B[N,K]^T + bias[N], fp16 mma m16n8k16, fp32 accumulate.
// CTA 128x128, 8 warps (2x4), warp tile 64x32, BK=64, 3-stage cp.async.
// XOR-swizzled fp16 tiles; fragments via ldmatrix.x4 (conflict-free).
// 2 CTAs/SM. Output type templated (fp16 for qkv, f32 for final).
// ---------------------------------------------------------------------------
template <typename OT>
__global__ __launch_bounds__(256, 2) void hgemm_nt_bias(
    const __half* __restrict__ A, const __half* __restrict__ B,
    const float* __restrict__ bias, OT* __restrict__ C,
    int M, int N, int K)
{
    extern __shared__ __align__(16) char smc[];   // STAGES * STAGE_BYTES
    const uint32_t sbase = (uint32_t)__cvta_generic_to_shared(smc);

    const int tid  = threadIdx.x;
    const int wid  = tid >> 5;
    const int lane = tid & 31;
    const int grp  = lane >> 2;      // 0..7
    const int qid  = lane & 3;       // 0..3

    const int wm = (wid & 1) * 64;   // warp rows
    const int wn = (wid >> 1) * 32;  // warp cols

    const __half* Ab = A + (size_t)blockIdx.y * CTA_M * K;
    const __half* Bb = B + (size_t)blockIdx.x * CTA_N * K;

    // staging decode: thread -> (row sr + 32p, 16B-unit su)
    const int su = tid & 7;
    const int sr = tid >> 3;         // 0..31

    // ldmatrix per-thread row/unit decode
    const int a_r = (lane & 7) + ((lane >> 3) & 1) * 8;  // A: m0,m1=rows, m2,m3=+unit
    const int a_u = lane >> 4;
    const int b_r = (lane & 7) + ((lane >> 4) & 1) * 8;  // B: m0,m1=units, m2,m3=+rows
    const int b_u = (lane >> 3) & 1;

    float acc[4][4][4];
#pragma unroll
    for (int i = 0; i < 4; i++)
#pragma unroll
        for (int j = 0; j < 4; j++)
#pragma unroll
            for (int c = 0; c < 4; c++) acc[i][j][c] = 0.f;

    const int nk = K / BK;

#define ISSUE_STAGE(kt_)                                                       \
    do {                                                                       \
        const uint32_t sb = sbase + ((kt_) % STAGES) * STAGE_BYTES;            \
        const int k0 = (kt_) * BK;                                             \
        _Pragma("unroll") for (int p = 0; p < 4; p++) {                        \
            const int r = sr + p * 32;                                         \
            const uint32_t sw = (uint32_t)(r * 128 + ((su ^ (r & 7)) << 4));   \
            cp16(sb + sw, Ab + (size_t)r * K + k0 + su * 8);                   \
            cp16(sb + A_BYTES + sw, Bb + (size_t)r * K + k0 + su * 8);         \
        }                                                                      \
        asm volatile("cp.async.commit_group;" ::: "memory");                   \
    } while (0)

    ISSUE_STAGE(0);
    ISSUE_STAGE(1);

    for (int kt = 0; kt < nk; kt++) {
        if (kt + 2 < nk) asm volatile("cp.async.wait_group 1;" ::: "memory");
        else             asm volatile("cp.async.wait_group 0;" ::: "memory");
        __syncthreads();
        if (kt + 2 < nk) ISSUE_STAGE(kt + 2);

        const uint32_t abase = sbase + (kt % STAGES) * STAGE_BYTES;
        const uint32_t bbase = abase + A_BYTES;

#pragma unroll
        for (int kk = 0; kk < 4; kk++) {
            uint32_t a[4][4], b[2][4];
#pragma unroll
            for (int mf = 0; mf < 4; mf++) {
                const int r = wm + mf * 16 + a_r;
                const int u = kk * 2 + a_u;
                LDSM4(a[mf], abase + r * 128 + ((u ^ (r & 7)) << 4));
            }
#pragma unroll
            for (int nfp = 0; nfp < 2; nfp++) {
                const int r = wn + nfp * 16 + b_r;
                const int u = kk * 2 + b_u;
                LDSM4(b[nfp], bbase + r * 128 + ((u ^ (r & 7)) << 4));
            }
#pragma unroll
            for (int mf = 0; mf < 4; mf++)
#pragma unroll
                for (int nf = 0; nf < 4; nf++) {
                    asm volatile(
                        "mma.sync.aligned.m16n8k16.row.col.f32.f16.f16.f32 "
                        "{%0,%1,%2,%3}, {%4,%5,%6,%7}, {%8,%9}, {%0,%1,%2,%3};"
                        : "+f"(acc[mf][nf][0]), "+f"(acc[mf][nf][1]),
                          "+f"(acc[mf][nf][2]), "+f"(acc[mf][nf][3])
                        : "r"(a[mf][0]), "r"(a[mf][1]),
                          "r"(a[mf][2]), "r"(a[mf][3]),
                          "r"(b[nf >> 1][(nf & 1) * 2]),
                          "r"(b[nf >> 1][(nf & 1) * 2 + 1]));
                }
        }
    }

    // epilogue: bias + stores (f32 -> float2, fp16 -> half2)
#pragma unroll
    for (int mf = 0; mf < 4; mf++) {
        const int row0 = blockIdx.y * CTA_M + wm + mf * 16 + grp;
#pragma unroll
        for (int nf = 0; nf < 4; nf++) {
            const int col = blockIdx.x * CTA_N + wn + nf * 8 + qid * 2;
            const float bv0 = bias[col], bv1 = bias[col + 1];
            float o00 = acc[mf][nf][0] + bv0, o01 = acc[mf][nf][1] + bv1;
            float o10 = acc[mf][nf][2] + bv0, o11 = acc[mf][nf][3] + bv1;
            if constexpr (sizeof(OT) == 2) {
                *(__half2*)((__half*)C + (size_t)row0 * N + col) =
                    __floats2half2_rn(o00, o01);
                *(__half2*)((__half*)C + (size_t)(row0 + 8) * N + col) =
                    __floats2half2_rn(o10, o11);
            } else {
                *(float2*)((float*)C + (size_t)row0 * N + col) =
                    make_float2(o00, o01);
                *(float2*)((float*)C + (size_t)(row0 + 8) * N + col) =
                    make_float2(o10, o11);
            }
        }
    }
#undef ISSUE_STAGE
}

// ---------------------------------------------------------------------------
// Windowed attention: one block per qkv row r = (n*64+w)*8 + b.
// fp16 input (half2 vectorized loads), f32 smem/compute, warp-shuffle
// softmax, fp16 scatter into the rearranged (nw*H, b, W*DH) layout.
// ---------------------------------------------------------------------------
__global__ __launch_bounds__(256) void attn_kernel(const __half* __restrict__ qkv,
                                                   __half* __restrict__ O2)
{
    __shared__ float qs[16 * 84];   // stride 84 breaks bank conflicts
    __shared__ float ks[16 * 84];
    __shared__ float vs[16 * 84];
    __shared__ float sc[16][17];

    const int r    = blockIdx.x;
    const int b    = r & 7;
    const int sidx = r >> 3;
    const int w    = sidx & 63;
    const int n    = sidx >> 6;
    const int tid  = threadIdx.x;

    // load q,k,v: 640 half2 each, convert to f32 smem
    const __half2* row2 = (const __half2*)(qkv + (size_t)r * 3840);
#pragma unroll
    for (int it = 0; it < 3; it++) {
        int i = tid + it * 256;
        if (i < 640) {
            int h = i / 40, d = (i % 40) * 2;
            float2 q = __half22float2(row2[i]);
            float2 k = __half22float2(row2[640 + i]);
            float2 v = __half22float2(row2[1280 + i]);
            qs[h * 84 + d] = q.x; qs[h * 84 + d + 1] = q.y;
            ks[h * 84 + d] = k.x; ks[h * 84 + d + 1] = k.y;
            vs[h * 84 + d] = v.x; vs[h * 84 + d + 1] = v.y;
        }
    }
    __syncthreads();

    // scores + warp-shuffle softmax: thread (h,g); g = low 4 lane bits
    {
        const int h = tid >> 4, g = tid & 15;
        const float* qh = qs + h * 84;
        const float* kg = ks + g * 84;
        float s = 0.f;
#pragma unroll
        for (int d = 0; d < 80; d++) s = fmaf(qh[d], kg[d], s);
        s *= 0.11180339887498948f;   // 1/sqrt(80)
        float m = s;
#pragma unroll
        for (int o = 8; o; o >>= 1)
            m = fmaxf(m, __shfl_xor_sync(0xffffffffu, m, o));
        float e = expf(s - m);
        float sum = e;
#pragma unroll
        for (int o = 8; o; o >>= 1)
            sum += __shfl_xor_sync(0xffffffffu, sum, o);
        sc[h][g] = e / sum;
    }
    __syncthreads();

    // O[h,d] = sum_g P[h,g] * v[g,d]; scatter fp16
    __half* obase = O2 + ((size_t)(n * 16) * 8 + b) * 5120 + (size_t)w * 80;
    for (int i = tid; i < 1280; i += 256) {
        int h = i / 80, d = i - h * 80;
        float o = 0.f;
#pragma unroll
        for (int g = 0; g < 16; g++) o = fmaf(sc[h][g], vs[g * 84 + d], o);
        obase[(size_t)h * 8 * 5120 + d] = __float2half(o);
    }
}

// ---------------------------------------------------------------------------
// Launcher
// Inputs: 0=x (4096,8,1280) f32, 1=cu_seqlens i64 (ignored), 2=qkv_w (3840,1280),
//         3=qkv_b (3840), 4=proj_w (1280,5120), 5=proj_b (1280)
// Output: (1024, 8, 1280) f32
// ---------------------------------------------------------------------------
extern "C" void kernel_launch(void* const* d_in, const int* in_sizes, int n_in,
                              void* d_out, int out_size)
{
    const float* x      = (const float*)d_in[0];
    const float* qkv_w  = (const float*)d_in[2];
    const float* qkv_b  = (const float*)d_in[3];
    const float* proj_w = (const float*)d_in[4];
    const float* proj_b = (const float*)d_in[5];
    float* out = (float*)d_out;

    __half *xh, *qkvwh, *projwh, *qkvh, *attnh;
    cudaGetSymbolAddress((void**)&xh, g_xh);
    cudaGetSymbolAddress((void**)&qkvwh, g_qkvwh);
    cudaGetSymbolAddress((void**)&projwh, g_projwh);
    cudaGetSymbolAddress((void**)&qkvh, g_qkvh);
    cudaGetSymbolAddress((void**)&attnh, g_attnh);

    const int smem_bytes = STAGES * STAGE_BYTES;   // 98304
    cudaFuncSetAttribute(hgemm_nt_bias<__half>,
                         cudaFuncAttributeMaxDynamicSharedMemorySize, smem_bytes);
    cudaFuncSetAttribute(hgemm_nt_bias<float>,
                         cudaFuncAttributeMaxDynamicSharedMemorySize, smem_bytes);

    // 0) convert inputs to fp16
    f2h_kernel<<<20480, 256>>>(x, xh, 41943040);
    f2h_kernel<<<2400, 256>>>(qkv_w, qkvwh, 4915200);
    f2h_kernel<<<3200, 256>>>(proj_w, projwh, 6553600);

    // 1) QKV projection: (32768 x 1280) @ (3840 x 1280)^T + bias -> fp16
    hgemm_nt_bias<__half><<<dim3(3840 / CTA_N, 32768 / CTA_M), 256, smem_bytes>>>(
        xh, qkvwh, qkv_b, qkvh, 32768, 3840, 1280);

    // 2) Windowed attention over head axis, scatter fp16 rearranged layout
    attn_kernel<<<32768, 256>>>(qkvh, attnh);

    // 3) Output projection: (8192 x 5120) @ (1280 x 5120)^T + bias -> d_out
    hgemm_nt_bias<float><<<dim3(1280 / CTA_N, 8192 / CTA_M), 256, smem_bytes>>>(
        attnh, projwh, proj_b, out, 8192, 1280, 5120);
}

// round 11
// speedup vs baseline: 3.9846x; 1.0492x over previous
#include <cuda_runtime.h>
#include <cuda_fp16.h>
#include <math.h>
#include <stdint.h>

// Problem: s=4096, b=8, D=1280, H=16, DH=80, W=64, nw=64
// QKV GEMM : M=32768, N=3840, K=1280  (NT, both K-major) -> fp16 out
// ATTN     : 32768 independent 16x16x80 attention problems (fp16 in/out)
// PROJ GEMM: M=8192,  N=1280, K=5120  (NT) -> f32 out
#define CTA_M 128
#define CTA_N 128
#define BK 64
#define STAGES 3
#define A_BYTES 16384              // 128 rows * 128B (64 halves)
#define STAGE_BYTES 32768          // A 16KB + B 16KB

// Scratch (device globals; no runtime allocation allowed)
__device__ __half g_xh[41943040ull];     // x as fp16
__device__ __half g_qkvwh[4915200ull];   // qkv_w as fp16
__device__ __half g_projwh[6553600ull];  // proj_w as fp16
__device__ __half g_qkvh[125829120ull];  // qkv output (fp16, attn input)
__device__ __half g_attnh[41943040ull];  // attn output, rearranged, fp16

__device__ __forceinline__ void cp16(uint32_t smem_dst, const void* gptr) {
    asm volatile("cp.async.cg.shared.global [%0], [%1], 16;"
                 :: "r"(smem_dst), "l"(gptr) : "memory");
}
#define LDSM4(d, addr)                                                         \
    asm volatile("ldmatrix.sync.aligned.m8n8.x4.shared.b16 {%0,%1,%2,%3}, [%4];" \
                 : "=r"((d)[0]), "=r"((d)[1]), "=r"((d)[2]), "=r"((d)[3])      \
                 : "r"(addr))

// ---------------------------------------------------------------------------
// f32 -> fp16 elementwise convert (8 elems/thread)
// ---------------------------------------------------------------------------
__global__ void f2h_kernel(const float* __restrict__ in,
                           __half* __restrict__ out, int n) {
    int i = (blockIdx.x * blockDim.x + threadIdx.x) * 8;
    if (i < n) {
        float4 v0 = *(const float4*)(in + i);
        float4 v1 = *(const float4*)(in + i + 4);
        __half2 h[4];
        h[0] = __floats2half2_rn(v0.x, v0.y);
        h[1] = __floats2half2_rn(v0.z, v0.w);
        h[2] = __floats2half2_rn(v1.x, v1.y);
        h[3] = __floats2half2_rn(v1.z, v1.w);
        *(uint4*)(out + i) = *(uint4*)h;
    }
}

// ---------------------------------------------------------------------------
// C[M,N] = A[M,K] * B[N,K]^T + bias[N], fp16 mma m16n8k16, fp32 accumulate.
// CTA 128x128, 8 warps (2x4), warp tile 64x32, BK=64, 3-stage cp.async.
// XOR-swizzled fp16 tiles; fragments via ldmatrix.x4 (conflict-free).
// 2 CTAs/SM. Output type templated (fp16 for qkv, f32 for final).
// ---------------------------------------------------------------------------
template <typename OT>
__global__ __launch_bounds__(256, 2) void hgemm_nt_bias(
    const __half* __restrict__ A, const __half* __restrict__ B,
    const float* __restrict__ bias, OT* __restrict__ C,
    int M, int N, int K)
{
    extern __shared__ __align__(16) char smc[];   // STAGES * STAGE_BYTES
    const uint32_t sbase = (uint32_t)__cvta_generic_to_shared(smc);

    const int tid  = threadIdx.x;
    const int wid  = tid >> 5;
    const int lane = tid & 31;
    const int grp  = lane >> 2;      // 0..7
    const int qid  = lane & 3;       // 0..3

    const int wm = (wid & 1) * 64;   // warp rows
    const int wn = (wid >> 1) * 32;  // warp cols

    const __half* Ab = A + (size_t)blockIdx.y * CTA_M * K;
    const __half* Bb = B + (size_t)blockIdx.x * CTA_N * K;

    // staging decode: thread -> (row sr + 32p, 16B-unit su)
    const int su = tid & 7;
    const int sr = tid >> 3;         // 0..31

    // ldmatrix per-thread row/unit decode
    const int a_r = (lane & 7) + ((lane >> 3) & 1) * 8;  // A: m0,m1=rows, m2,m3=+unit
    const int a_u = lane >> 4;
    const int b_r = (lane & 7) + ((lane >> 4) & 1) * 8;  // B: m0,m1=units, m2,m3=+rows
    const int b_u = (lane >> 3) & 1;

    float acc[4][4][4];
#pragma unroll
    for (int i = 0; i < 4; i++)
#pragma unroll
        for (int j = 0; j < 4; j++)
#pragma unroll
            for (int c = 0; c < 4; c++) acc[i][j][c] = 0.f;

    const int nk = K / BK;

#define ISSUE_STAGE(kt_)                                                       \
    do {                                                                       \
        const uint32_t sb = sbase + ((kt_) % STAGES) * STAGE_BYTES;            \
        const int k0 = (kt_) * BK;                                             \
        _Pragma("unroll") for (int p = 0; p < 4; p++) {                        \
            const int r = sr + p * 32;                                         \
            const uint32_t sw = (uint32_t)(r * 128 + ((su ^ (r & 7)) << 4));   \
            cp16(sb + sw, Ab + (size_t)r * K + k0 + su * 8);                   \
            cp16(sb + A_BYTES + sw, Bb + (size_t)r * K + k0 + su * 8);         \
        }                                                                      \
        asm volatile("cp.async.commit_group;" ::: "memory");                   \
    } while (0)

    ISSUE_STAGE(0);
    ISSUE_STAGE(1);

    for (int kt = 0; kt < nk; kt++) {
        if (kt + 2 < nk) asm volatile("cp.async.wait_group 1;" ::: "memory");
        else             asm volatile("cp.async.wait_group 0;" ::: "memory");
        __syncthreads();
        if (kt + 2 < nk) ISSUE_STAGE(kt + 2);

        const uint32_t abase = sbase + (kt % STAGES) * STAGE_BYTES;
        const uint32_t bbase = abase + A_BYTES;

#pragma unroll
        for (int kk = 0; kk < 4; kk++) {
            uint32_t a[4][4], b[2][4];
#pragma unroll
            for (int mf = 0; mf < 4; mf++) {
                const int r = wm + mf * 16 + a_r;
                const int u = kk * 2 + a_u;
                LDSM4(a[mf], abase + r * 128 + ((u ^ (r & 7)) << 4));
            }
#pragma unroll
            for (int nfp = 0; nfp < 2; nfp++) {
                const int r = wn + nfp * 16 + b_r;
                const int u = kk * 2 + b_u;
                LDSM4(b[nfp], bbase + r * 128 + ((u ^ (r & 7)) << 4));
            }
#pragma unroll
            for (int mf = 0; mf < 4; mf++)
#pragma unroll
                for (int nf = 0; nf < 4; nf++) {
                    asm volatile(
                        "mma.sync.aligned.m16n8k16.row.col.f32.f16.f16.f32 "
                        "{%0,%1,%2,%3}, {%4,%5,%6,%7}, {%8,%9}, {%0,%1,%2,%3};"
                        : "+f"(acc[mf][nf][0]), "+f"(acc[mf][nf][1]),
                          "+f"(acc[mf][nf][2]), "+f"(acc[mf][nf][3])
                        : "r"(a[mf][0]), "r"(a[mf][1]),
                          "r"(a[mf][2]), "r"(a[mf][3]),
                          "r"(b[nf >> 1][(nf & 1) * 2]),
                          "r"(b[nf >> 1][(nf & 1) * 2 + 1]));
                }
        }
    }

    // epilogue: bias + stores (f32 -> float2, fp16 -> half2)
#pragma unroll
    for (int mf = 0; mf < 4; mf++) {
        const int row0 = blockIdx.y * CTA_M + wm + mf * 16 + grp;
#pragma unroll
        for (int nf = 0; nf < 4; nf++) {
            const int col = blockIdx.x * CTA_N + wn + nf * 8 + qid * 2;
            const float bv0 = bias[col], bv1 = bias[col + 1];
            float o00 = acc[mf][nf][0] + bv0, o01 = acc[mf][nf][1] + bv1;
            float o10 = acc[mf][nf][2] + bv0, o11 = acc[mf][nf][3] + bv1;
            if constexpr (sizeof(OT) == 2) {
                *(__half2*)((__half*)C + (size_t)row0 * N + col) =
                    __floats2half2_rn(o00, o01);
                *(__half2*)((__half*)C + (size_t)(row0 + 8) * N + col) =
                    __floats2half2_rn(o10, o11);
            } else {
                *(float2*)((float*)C + (size_t)row0 * N + col) =
                    make_float2(o00, o01);
                *(float2*)((float*)C + (size_t)(row0 + 8) * N + col) =
                    make_float2(o10, o11);
            }
        }
    }
#undef ISSUE_STAGE
}

// ---------------------------------------------------------------------------
// Windowed attention: one block per qkv row r = (n*64+w)*8 + b.
// fp16 input (half2 loads), f32 smem/compute, warp-shuffle softmax.
// ILP-optimized: 4-chain score dot products; PV with fixed (h, d-lane)
// mapping, softmax row hoisted to registers, 2 independent FMA chains.
// ---------------------------------------------------------------------------
__global__ __launch_bounds__(256) void attn_kernel(const __half* __restrict__ qkv,
                                                   __half* __restrict__ O2)
{
    __shared__ float qs[16 * 84];   // stride 84 breaks bank conflicts
    __shared__ float ks[16 * 84];
    __shared__ float vs[16 * 84];
    __shared__ float sc[16][17];

    const int r    = blockIdx.x;
    const int b    = r & 7;
    const int sidx = r >> 3;
    const int w    = sidx & 63;
    const int n    = sidx >> 6;
    const int tid  = threadIdx.x;

    // load q,k,v: 640 half2 each, convert to f32 smem
    const __half2* row2 = (const __half2*)(qkv + (size_t)r * 3840);
#pragma unroll
    for (int it = 0; it < 3; it++) {
        int i = tid + it * 256;
        if (i < 640) {
            int h = i / 40, d = (i % 40) * 2;
            float2 q = __half22float2(row2[i]);
            float2 k = __half22float2(row2[640 + i]);
            float2 v = __half22float2(row2[1280 + i]);
            qs[h * 84 + d] = q.x; qs[h * 84 + d + 1] = q.y;
            ks[h * 84 + d] = k.x; ks[h * 84 + d + 1] = k.y;
            vs[h * 84 + d] = v.x; vs[h * 84 + d + 1] = v.y;
        }
    }
    __syncthreads();

    // scores (4 independent chains) + warp-shuffle softmax over g = lane&15
    {
        const int h = tid >> 4, g = tid & 15;
        const float* qh = qs + h * 84;
        const float* kg = ks + g * 84;
        float s0 = 0.f, s1 = 0.f, s2 = 0.f, s3 = 0.f;
#pragma unroll
        for (int d = 0; d < 80; d += 4) {
            s0 = fmaf(qh[d],     kg[d],     s0);
            s1 = fmaf(qh[d + 1], kg[d + 1], s1);
            s2 = fmaf(qh[d + 2], kg[d + 2], s2);
            s3 = fmaf(qh[d + 3], kg[d + 3], s3);
        }
        float s = ((s0 + s1) + (s2 + s3)) * 0.11180339887498948f;
        float m = s;
#pragma unroll
        for (int o = 8; o; o >>= 1)
            m = fmaxf(m, __shfl_xor_sync(0xffffffffu, m, o));
        float e = expf(s - m);
        float sum = e;
#pragma unroll
        for (int o = 8; o; o >>= 1)
            sum += __shfl_xor_sync(0xffffffffu, sum, o);
        sc[h][g] = e / sum;
    }
    __syncthreads();

    // PV: thread (h = tid>>4, dlane = tid&15) handles d = dlane + 16j, j=0..4.
    // softmax row in registers (broadcast LDS), 2 independent FMA chains.
    {
        const int h = tid >> 4, dl = tid & 15;
        float p[16];
#pragma unroll
        for (int g = 0; g < 16; g++) p[g] = sc[h][g];
        __half* orow = O2 + ((size_t)(n * 16 + h) * 8 + b) * 5120 + (size_t)w * 80;
#pragma unroll
        for (int j = 0; j < 5; j++) {
            const int d = dl + j * 16;
            const float* vcol = vs + d;
            float o0 = 0.f, o1 = 0.f;
#pragma unroll
            for (int g = 0; g < 16; g += 2) {
                o0 = fmaf(p[g],     vcol[g * 84],       o0);
                o1 = fmaf(p[g + 1], vcol[(g + 1) * 84], o1);
            }
            orow[d] = __float2half(o0 + o1);
        }
    }
}

// ---------------------------------------------------------------------------
// Launcher
// Inputs: 0=x (4096,8,1280) f32, 1=cu_seqlens i64 (ignored), 2=qkv_w (3840,1280),
//         3=qkv_b (3840), 4=proj_w (1280,5120), 5=proj_b (1280)
// Output: (1024, 8, 1280) f32
// ---------------------------------------------------------------------------
extern "C" void kernel_launch(void* const* d_in, const int* in_sizes, int n_in,
                              void* d_out, int out_size)
{
    const float* x      = (const float*)d_in[0];
    const float* qkv_w  = (const float*)d_in[2];
    const float* qkv_b  = (const float*)d_in[3];
    const float* proj_w = (const float*)d_in[4];
    const float* proj_b = (const float*)d_in[5];
    float* out = (float*)d_out;

    __half *xh, *qkvwh, *projwh, *qkvh, *attnh;
    cudaGetSymbolAddress((void**)&xh, g_xh);
    cudaGetSymbolAddress((void**)&qkvwh, g_qkvwh);
    cudaGetSymbolAddress((void**)&projwh, g_projwh);
    cudaGetSymbolAddress((void**)&qkvh, g_qkvh);
    cudaGetSymbolAddress((void**)&attnh, g_attnh);

    const int smem_bytes = STAGES * STAGE_BYTES;   // 98304
    cudaFuncSetAttribute(hgemm_nt_bias<__half>,
                         cudaFuncAttributeMaxDynamicSharedMemorySize, smem_bytes);
    cudaFuncSetAttribute(hgemm_nt_bias<float>,
                         cudaFuncAttributeMaxDynamicSharedMemorySize, smem_bytes);

    // 0) convert inputs to fp16
    f2h_kernel<<<20480, 256>>>(x, xh, 41943040);
    f2h_kernel<<<2400, 256>>>(qkv_w, qkvwh, 4915200);
    f2h_kernel<<<3200, 256>>>(proj_w, projwh, 6553600);

    // 1) QKV projection: (32768 x 1280) @ (3840 x 1280)^T + bias -> fp16
    hgemm_nt_bias<__half><<<dim3(3840 / CTA_N, 32768 / CTA_M), 256, smem_bytes>>>(
        xh, qkvwh, qkv_b, qkvh, 32768, 3840, 1280);

    // 2) Windowed attention over head axis, scatter fp16 rearranged layout
    attn_kernel<<<32768, 256>>>(qkvh, attnh);

    // 3) Output projection: (8192 x 5120) @ (1280 x 5120)^T + bias -> d_out
    hgemm_nt_bias<float><<<dim3(1280 / CTA_N, 8192 / CTA_M), 256, smem_bytes>>>(
        attnh, projwh, proj_b, out, 8192, 1280, 5120);
}